// round 11
// baseline (speedup 1.0000x reference)
#include <cuda_runtime.h>
#include <cstdint>

#define BATCH   32
#define SEQLEN  4096
#define CIN     7
#define OUTC    512
#define NKERN   74
#define TB      128                  // timesteps per block
#define NT      256                  // threads per block (1 output pair each)
#define T       16                   // output timesteps per accumulator chunk
#define SROWS   (TB + 24)            // 152 smem rows
#define NCOMBO  11                   // distinct (cA,cB) channel pairs

// ---- dynamic smem layout (byte offsets) ----
#define SM_PK   0                            // float2 pk[11][152]      = 13376
#define SM_KS   (NCOMBO * SROWS * 8)         // float  ks[74*24]        = 7104
#define SM_U    (SM_KS + NKERN * 24 * 4)     // 20480: union xs[7][152] | wpk
#define SM_WPK  SM_U                         // float2 wpk[24][256]     = 49152
#define SMEM_TOTAL (SM_U + 24 * NT * 8)      // 69632

// ---------- packed f32x2 helpers ----------
__device__ __forceinline__ unsigned long long pack2(float lo, float hi) {
    unsigned long long r;
    asm("mov.b64 %0, {%1, %2};" : "=l"(r) : "f"(lo), "f"(hi));
    return r;
}
__device__ __forceinline__ void fma2(unsigned long long& acc,
                                     unsigned long long a, unsigned long long b) {
    asm("fma.rn.f32x2 %0, %1, %2, %0;" : "+l"(acc) : "l"(a), "l"(b));
}
__device__ __forceinline__ uint32_t smem_u32(const void* p) {
    uint32_t a;
    asm("{ .reg .u64 t; cvta.to.shared.u64 t, %1; cvt.u32.u64 %0, t; }" : "=r"(a) : "l"(p));
    return a;
}
// volatile loads: pinned in program order -> guaranteed back-to-back batch (MLP)
__device__ __forceinline__ unsigned long long lds64v(uint32_t addr) {
    unsigned long long r;
    asm volatile("ld.volatile.shared.b64 %0, [%1];" : "=l"(r) : "r"(addr));
    return r;
}
__device__ __forceinline__ float4 lds128v(uint32_t addr) {
    float4 v;
    asm volatile("ld.volatile.shared.v4.f32 {%0,%1,%2,%3}, [%4];"
                 : "=f"(v.x), "=f"(v.y), "=f"(v.z), "=f"(v.w) : "r"(addr));
    return v;
}

// Dense 24-tap FIR: out[b,t,o] = sum_{d=0}^{23} W[o,d] * x[b, t+d-22, c(o)]
// tap d maps to kernel (i,j): o=d-22, i=(1-o)/3, j=o+1+3i.  j==2 <=> d%3==2.

__global__ __launch_bounds__(NT, 2)
void conv_main(const float* __restrict__ x, const float* __restrict__ kern,
               float* __restrict__ out) {
    extern __shared__ char smem[];
    float2* pk  = (float2*)(smem + SM_PK);    // [11][152]
    float*  ks  = (float*)(smem + SM_KS);     // [74*24]
    float*  xs  = (float*)(smem + SM_U);      // [7][152]  (union with wpk)
    float2* wpk = (float2*)(smem + SM_WPK);   // [24][256]
    const uint32_t sb = smem_u32(smem);

    const int nt_tiles = SEQLEN / TB;         // 32
    const int b   = blockIdx.x / nt_tiles;
    const int t0  = (blockIdx.x % nt_tiles) * TB;
    const int tid = threadIdx.x;

    // ---- phase 1: raw x window + kernel weights ----
    {
        const float* xb = x + (size_t)b * SEQLEN * CIN;
        for (int idx = tid; idx < CIN * SROWS; idx += NT) {
            int r = idx / CIN;
            int c = idx % CIN;
            int g = t0 - 22 + r;
            float v = 0.0f;
            if (g >= 0 && g < SEQLEN) v = xb[(size_t)g * CIN + c];
            xs[c * SROWS + r] = v;
        }
        for (int idx = tid; idx < NKERN * 24; idx += NT)
            ks[idx] = kern[idx];
    }
    __syncthreads();

    // ---- phase 2: packed channel-pair arrays ----
    for (int idx = tid; idx < NCOMBO * SROWS; idx += NT) {
        int cm = idx / SROWS, r = idx % SROWS;
        int ca, cb;
        if (cm < 7)       { ca = cm;           cb = cm; }
        else if (cm < 10) { ca = 2 * (cm - 7); cb = ca + 1; }
        else              { ca = 6;            cb = 0; }
        pk[cm * SROWS + r] = make_float2(xs[ca * SROWS + r], xs[cb * SROWS + r]);
    }
    __syncthreads();     // wpk may now overwrite xs

    // ---- output pair assignment ----
    const int o0 = 2 * tid;
    const int o1 = o0 + 1;
    const int cA = o0 / 73, kA = o0 % 73;
    int cB, kB;
    if (o1 == 511) { cB = 0; kB = 73; } else { cB = o1 / 73; kB = o1 % 73; }

    int combo;
    if (cA == cB)        combo = cA;
    else if (o1 == 511)  combo = 10;
    else                 combo = 7 + (cA >> 1);

    // ---- phase 3: per-thread packed weight table (own slot; no sync needed) ----
#pragma unroll
    for (int d = 0; d < 24; d++) {
        const int o = d - 22;
        const int i = (1 - o) / 3;
        const int j = o + 1 + 3 * i;
        wpk[d * NT + tid] = make_float2(ks[kA * 24 + i * 3 + j],
                                        ks[kB * 24 + i * 3 + j]);
    }

    const uint32_t pkb   = sb + SM_PK + (uint32_t)combo * (SROWS * 8);
    const uint32_t wbase = sb + SM_WPK + (uint32_t)tid * 8;
    float* op = out + ((size_t)b * SEQLEN + t0) * OUTC + o0;

    // ---- streaming FIR: per chunk, 2 weight passes x 2 batched row loads ----
#pragma unroll 1
    for (int cbase = 0; cbase < TB; cbase += T) {
        const uint32_t cb_addr = pkb + (uint32_t)(cbase >> 1) * 16;
        unsigned long long acc[T];
#pragma unroll
        for (int tr = 0; tr < T; tr++) acc[tr] = 0ull;

        // ======== pass 0: taps 0..11 (rows 0..27 -> q 0..13) ========
        {
            unsigned long long wp[12];
#pragma unroll
            for (int k = 0; k < 12; k++) wp[k] = lds64v(wbase + k * (NT * 8));

            float4 q[7];
#pragma unroll
            for (int i = 0; i < 7; i++) q[i] = lds128v(cb_addr + i * 16);   // batch A
#pragma unroll
            for (int qi = 0; qi < 7; qi++) {
                const unsigned long long px0 = pack2(q[qi].x, q[qi].y);
                const unsigned long long px1 = pack2(q[qi].z, q[qi].w);
                const int gg = 2 * qi;
#pragma unroll
                for (int tr = 0; tr < T; tr++) {
                    const int d0 = gg - tr;
                    if (d0 >= 0 && d0 < 12) fma2(acc[tr], px0, wp[d0]);
                    const int d1 = gg + 1 - tr;
                    if (d1 >= 0 && d1 < 12) fma2(acc[tr], px1, wp[d1]);
                }
            }
#pragma unroll
            for (int i = 0; i < 7; i++) q[i] = lds128v(cb_addr + (7 + i) * 16);  // batch B
#pragma unroll
            for (int qi = 0; qi < 7; qi++) {
                const unsigned long long px0 = pack2(q[qi].x, q[qi].y);
                const unsigned long long px1 = pack2(q[qi].z, q[qi].w);
                const int gg = 14 + 2 * qi;
#pragma unroll
                for (int tr = 0; tr < T; tr++) {
                    const int d0 = gg - tr;
                    if (d0 >= 0 && d0 < 12) fma2(acc[tr], px0, wp[d0]);
                    const int d1 = gg + 1 - tr;
                    if (d1 >= 0 && d1 < 12) fma2(acc[tr], px1, wp[d1]);
                }
            }
        }
        // ======== pass 1: taps 12..23 (rows 12..39 -> q 6..19) ========
        {
            unsigned long long wp[12];
#pragma unroll
            for (int k = 0; k < 12; k++) wp[k] = lds64v(wbase + (12 + k) * (NT * 8));

            float4 q[7];
#pragma unroll
            for (int i = 0; i < 7; i++) q[i] = lds128v(cb_addr + (6 + i) * 16);  // batch C
#pragma unroll
            for (int qi = 0; qi < 7; qi++) {
                const unsigned long long px0 = pack2(q[qi].x, q[qi].y);
                const unsigned long long px1 = pack2(q[qi].z, q[qi].w);
                const int gg = 12 + 2 * qi;
#pragma unroll
                for (int tr = 0; tr < T; tr++) {
                    const int d0 = gg - tr;
                    if (d0 >= 12 && d0 < 24) fma2(acc[tr], px0, wp[d0 - 12]);
                    const int d1 = gg + 1 - tr;
                    if (d1 >= 12 && d1 < 24) fma2(acc[tr], px1, wp[d1 - 12]);
                }
            }
#pragma unroll
            for (int i = 0; i < 7; i++) q[i] = lds128v(cb_addr + (13 + i) * 16); // batch D
#pragma unroll
            for (int qi = 0; qi < 7; qi++) {
                const unsigned long long px0 = pack2(q[qi].x, q[qi].y);
                const unsigned long long px1 = pack2(q[qi].z, q[qi].w);
                const int gg = 26 + 2 * qi;
#pragma unroll
                for (int tr = 0; tr < T; tr++) {
                    const int d0 = gg - tr;
                    if (d0 >= 12 && d0 < 24) fma2(acc[tr], px0, wp[d0 - 12]);
                    const int d1 = gg + 1 - tr;
                    if (d1 >= 12 && d1 < 24) fma2(acc[tr], px1, wp[d1 - 12]);
                }
            }
        }

#pragma unroll
        for (int tr = 0; tr < T; tr++)
            *reinterpret_cast<unsigned long long*>(op + (size_t)tr * OUTC) = acc[tr];
        op += (size_t)T * OUTC;
    }

    // ---- folded t = L-1 fix: right padding drops all j==2 taps (d%3==2) ----
    if (t0 + TB == SEQLEN) {
        float sA = 0.0f, sB = 0.0f;
#pragma unroll
        for (int d = 0; d < 24; d++) {
            if (d % 3 != 2) {
                const float2 w = wpk[d * NT + tid];
                const float2 v = pk[combo * SROWS + 127 + d];
                sA += v.x * w.x;
                sB += v.y * w.y;
            }
        }
        *reinterpret_cast<unsigned long long*>(
            out + ((size_t)b * SEQLEN + (SEQLEN - 1)) * OUTC + o0) = pack2(sA, sB);
    }
}

extern "C" void kernel_launch(void* const* d_in, const int* in_sizes, int n_in,
                              void* d_out, int out_size) {
    const float* x    = (const float*)d_in[0];   // (32, 4096, 7) f32
    const float* kern = (const float*)d_in[1];   // (74, 8, 3)  f32
    float* out        = (float*)d_out;           // (32, 4096, 512) f32

    cudaFuncSetAttribute(conv_main, cudaFuncAttributeMaxDynamicSharedMemorySize,
                         SMEM_TOTAL);
    conv_main<<<BATCH * (SEQLEN / TB), NT, SMEM_TOTAL>>>(x, kern, out);
}

// round 12
// speedup vs baseline: 1.2483x; 1.2483x over previous
#include <cuda_runtime.h>
#include <cstdint>

#define BATCH   32
#define SEQLEN  4096
#define CIN     7
#define OUTC    512
#define NKERN   74
#define TB      128                  // timesteps per tile
#define NTILES  (BATCH * (SEQLEN / TB))   // 1024
#define GRID    296                  // 148 SMs x occ 2: single resident wave
#define NT      256
#define T       16                   // outputs per accumulator chunk
#define SROWS   (TB + 24)            // 152
#define NCOMBO  11
#define XELEM   (CIN * SROWS)        // 1064
#define PFV     5                    // ceil(1064/256) prefetch regs

// ---------- packed f32x2 helpers ----------
__device__ __forceinline__ unsigned long long pack2(float lo, float hi) {
    unsigned long long r;
    asm("mov.b64 %0, {%1, %2};" : "=l"(r) : "f"(lo), "f"(hi));
    return r;
}
__device__ __forceinline__ void fma2(unsigned long long& acc,
                                     unsigned long long a, unsigned long long b) {
    asm("fma.rn.f32x2 %0, %1, %2, %0;" : "+l"(acc) : "l"(a), "l"(b));
}

// Dense 24-tap FIR: out[b,t,o] = sum_d W[o,d] * x[b, t+d-22, c(o)]
// tap d: o=d-22, i=(1-o)/3, j=o+1+3i.   j==2 <=> d%3==2.

__global__ __launch_bounds__(NT, 2)
void conv_main(const float* __restrict__ x, const float* __restrict__ kern,
               float* __restrict__ out) {
    __shared__ float xs[XELEM];                               // raw window (transient)
    __shared__ __align__(16) float2 pkb[2][NCOMBO][SROWS];    // double-buffered
    __shared__ float ks[NKERN * 24];

    const int tid = threadIdx.x;
    const int bid = blockIdx.x;

    // ---- one-time: output-pair assignment ----
    const int o0 = 2 * tid;
    const int o1 = o0 + 1;
    const int cA = o0 / 73, kA = o0 % 73;
    int cB, kB;
    if (o1 == 511) { cB = 0; kB = 73; } else { cB = o1 / 73; kB = o1 % 73; }
    int combo;
    if (cA == cB)        combo = cA;
    else if (o1 == 511)  combo = 10;
    else                 combo = 7 + (cA >> 1);

    // ---- one-time: ks into smem ----
    for (int idx = tid; idx < NKERN * 24; idx += NT) ks[idx] = kern[idx];

    // ---- one-time: load tile0 x window ----
    int tile = bid;
    {
        const int b0  = tile >> 5;
        const int t00 = (tile & 31) * TB;
        const float* xb = x + (size_t)b0 * SEQLEN * CIN;
        for (int idx = tid; idx < XELEM; idx += NT) {
            int r = idx / CIN, c = idx % CIN;
            int g = t00 - 22 + r;
            float v = 0.0f;
            if (g >= 0 && g < SEQLEN) v = xb[(size_t)g * CIN + c];
            xs[c * SROWS + r] = v;
        }
    }
    __syncthreads();

    // ---- one-time: packed weights in registers ----
    unsigned long long wreg[24];
#pragma unroll
    for (int d = 0; d < 24; d++) {
        const int o = d - 22;
        const int i = (1 - o) / 3;
        const int j = o + 1 + 3 * i;
        wreg[d] = pack2(ks[kA * 24 + i * 3 + j], ks[kB * 24 + i * 3 + j]);
    }

    // build pk buffer 0 from xs
    for (int idx = tid; idx < NCOMBO * SROWS; idx += NT) {
        int cm = idx / SROWS, r = idx % SROWS;
        int ca, cb;
        if (cm < 7)       { ca = cm;           cb = cm; }
        else if (cm < 10) { ca = 2 * (cm - 7); cb = ca + 1; }
        else              { ca = 6;            cb = 0; }
        pkb[0][cm][r] = make_float2(xs[ca * SROWS + r], xs[cb * SROWS + r]);
    }
    __syncthreads();

    int cur = 0;
    while (tile < NTILES) {
        const int b  = tile >> 5;
        const int tt = tile & 31;
        const int t0 = tt * TB;
        const int ntile = tile + GRID;
        const bool have = (ntile < NTILES);

        // ---- prefetch next tile's x window into registers (LDGs in flight
        //      across the FIR below; parked in 5 regs) ----
        float pv[PFV];
        if (have) {
            const int nb  = ntile >> 5;
            const int nt0 = (ntile & 31) * TB;
            const float* xb = x + (size_t)nb * SEQLEN * CIN;
#pragma unroll
            for (int k = 0; k < PFV; k++) {
                const int idx = tid + k * NT;
                float v = 0.0f;
                if (idx < XELEM) {
                    const int r = idx / CIN, c = idx % CIN;
                    const int g = nt0 - 22 + r;
                    if (g >= 0 && g < SEQLEN) v = xb[(size_t)g * CIN + c];
                }
                pv[k] = v;
            }
        }

        // ---- FIR over pk[cur] (R6 inner loop) ----
        const float4* pk4 = (const float4*)(pkb[cur][combo]);
        float* op = out + ((size_t)b * SEQLEN + t0) * OUTC + o0;
#pragma unroll 1
        for (int cbase = 0; cbase < TB; cbase += T) {
            unsigned long long acc[T];
#pragma unroll
            for (int tr = 0; tr < T; tr++) acc[tr] = 0ull;

#pragma unroll
            for (int gp = 0; gp < (T + 24) / 2; gp++) {       // 20 row-pairs
                const float4 q = pk4[(cbase >> 1) + gp];      // one LDS.128
                const unsigned long long px0 = pack2(q.x, q.y);
                const unsigned long long px1 = pack2(q.z, q.w);
                const int gg = 2 * gp;
#pragma unroll
                for (int tr = 0; tr < T; tr++) {
                    const int d0 = gg - tr;
                    if (d0 >= 0 && d0 < 24) fma2(acc[tr], px0, wreg[d0]);
                    const int d1 = gg + 1 - tr;
                    if (d1 >= 0 && d1 < 24) fma2(acc[tr], px1, wreg[d1]);
                }
            }
#pragma unroll
            for (int tr = 0; tr < T; tr++)
                *reinterpret_cast<unsigned long long*>(op + (size_t)tr * OUTC) = acc[tr];
            op += (size_t)T * OUTC;
        }

        // ---- t = L-1 fix (tiles with tt==31): j==2 taps dropped ----
        if (tt == 31) {
            const float2* pkc = pkb[cur][combo];
            float sA = 0.0f, sB = 0.0f;
#pragma unroll
            for (int i = 0; i < 8; i++)
#pragma unroll
                for (int j = 0; j < 2; j++) {
                    const int r = 149 + (j - 1) - 3 * i;
                    const float2 v = pkc[r];
                    sA += v.x * ks[kA * 24 + i * 3 + j];
                    sB += v.y * ks[kB * 24 + i * 3 + j];
                }
            *reinterpret_cast<unsigned long long*>(
                out + ((size_t)b * SEQLEN + (SEQLEN - 1)) * OUTC + o0) = pack2(sA, sB);
        }

        // ---- commit prefetch -> xs, build pk[1-cur] ----
        if (have) {
#pragma unroll
            for (int k = 0; k < PFV; k++) {
                const int idx = tid + k * NT;
                if (idx < XELEM) {
                    const int r = idx / CIN, c = idx % CIN;
                    xs[c * SROWS + r] = pv[k];
                }
            }
            __syncthreads();
            const int nxt = cur ^ 1;
            for (int idx = tid; idx < NCOMBO * SROWS; idx += NT) {
                int cm = idx / SROWS, r = idx % SROWS;
                int ca, cb;
                if (cm < 7)       { ca = cm;           cb = cm; }
                else if (cm < 10) { ca = 2 * (cm - 7); cb = ca + 1; }
                else              { ca = 6;            cb = 0; }
                pkb[nxt][cm][r] = make_float2(xs[ca * SROWS + r], xs[cb * SROWS + r]);
            }
            __syncthreads();
        }
        cur ^= 1;
        tile = ntile;
    }
}

extern "C" void kernel_launch(void* const* d_in, const int* in_sizes, int n_in,
                              void* d_out, int out_size) {
    const float* x    = (const float*)d_in[0];   // (32, 4096, 7) f32
    const float* kern = (const float*)d_in[1];   // (74, 8, 3)  f32
    float* out        = (float*)d_out;           // (32, 4096, 512) f32

    conv_main<<<GRID, NT>>>(x, kern, out);
}